// round 2
// baseline (speedup 1.0000x reference)
#include <cuda_runtime.h>

// SSIM, fully fused single pass. X,Y: f32[32,3,512,512] -> scalar mean SSIM.
//
// Per block: one image tile of 128 output cols x 32 output rows.
// Phase 1: horizontal 11-tap Gaussian of {x,y,x^2,y^2,xy} -> smem [5][42][128].
//          Tap-outer restructure: only 3 product registers live (no spill arrays).
// Phase 2: vertical 11-tap conv, split into two register-light passes:
//          pass A (mu1, mu2: 32 accs), pass B (sxx, syy, sxy: 48 accs).
// Epilogue folds [-1,1]->[0,1] normalization: mu' = (mu+1)/2, sigma' = sigma/4.
// Per-block partial sums -> __device__ array -> single reduce kernel (no atomics,
// no zeroing kernel).

#define TW 128
#define TH 32
#define NHR (TH + 10)   // 42
#define BX 32
#define BY 8
#define MAX_BLOCKS 16384

__device__ float g_partials[MAX_BLOCKS];

__global__ void __launch_bounds__(BX * BY, 2)
ssim_main_kernel(const float* __restrict__ X, const float* __restrict__ Y) {
    extern __shared__ float sh[];  // [5][NHR][TW] = 107520 B

    const float GW[11] = {
        0.00102838f, 0.00759876f, 0.03600079f, 0.10936072f, 0.21300555f,
        0.26601173f,
        0.21300555f, 0.10936072f, 0.03600079f, 0.00759876f, 0.00102838f};

    const int tx = threadIdx.x;
    const int ty = threadIdx.y;
    const int c0 = blockIdx.x * TW;
    const int r0 = blockIdx.y * TH;
    const long img = blockIdx.z;
    const float* __restrict__ Xi = X + img * (512L * 512L);
    const float* __restrict__ Yi = Y + img * (512L * 512L);
    const int basec = c0 + 4 * tx;

    // ---------------- Phase 1: horizontal pass into smem ----------------
    for (int hr = ty; hr < NHR; hr += BY) {
        const int gr = r0 + hr;
        if (gr < 512) {
            float xv[16], yv[16];
            const float* __restrict__ xr = Xi + (long)gr * 512;
            const float* __restrict__ yr = Yi + (long)gr * 512;
#pragma unroll
            for (int q = 0; q < 4; q++) {
                const int qc = basec + 4 * q;
                float4 xq, yq;
                if (qc < 512) {
                    xq = *reinterpret_cast<const float4*>(xr + qc);
                    yq = *reinterpret_cast<const float4*>(yr + qc);
                } else {
                    xq = make_float4(0.f, 0.f, 0.f, 0.f);
                    yq = make_float4(0.f, 0.f, 0.f, 0.f);
                }
                xv[4 * q + 0] = xq.x; xv[4 * q + 1] = xq.y;
                xv[4 * q + 2] = xq.z; xv[4 * q + 3] = xq.w;
                yv[4 * q + 0] = yq.x; yv[4 * q + 1] = yq.y;
                yv[4 * q + 2] = yq.z; yv[4 * q + 3] = yq.w;
            }
            float ax[4], ay[4], axx[4], ayy[4], axy[4];
#pragma unroll
            for (int j = 0; j < 4; j++) {
                ax[j] = 0.f; ay[j] = 0.f; axx[j] = 0.f; ayy[j] = 0.f; axy[j] = 0.f;
            }
            // Tap-outer: products are transient (3 regs), never an array.
#pragma unroll
            for (int t = 0; t < 14; t++) {
                const float xt = xv[t], yt = yv[t];
                const float pxx = xt * xt;
                const float pyy = yt * yt;
                const float pxy = xt * yt;
#pragma unroll
                for (int j = 0; j < 4; j++) {
                    const int k = t - j;
                    if (k >= 0 && k <= 10) {
                        const float w = GW[k];
                        ax[j]  = fmaf(w, xt,  ax[j]);
                        ay[j]  = fmaf(w, yt,  ay[j]);
                        axx[j] = fmaf(w, pxx, axx[j]);
                        ayy[j] = fmaf(w, pyy, ayy[j]);
                        axy[j] = fmaf(w, pxy, axy[j]);
                    }
                }
            }
            const int so = hr * TW + 4 * tx;
            *reinterpret_cast<float4*>(&sh[0 * NHR * TW + so]) = make_float4(ax[0], ax[1], ax[2], ax[3]);
            *reinterpret_cast<float4*>(&sh[1 * NHR * TW + so]) = make_float4(ay[0], ay[1], ay[2], ay[3]);
            *reinterpret_cast<float4*>(&sh[2 * NHR * TW + so]) = make_float4(axx[0], axx[1], axx[2], axx[3]);
            *reinterpret_cast<float4*>(&sh[3 * NHR * TW + so]) = make_float4(ayy[0], ayy[1], ayy[2], ayy[3]);
            *reinterpret_cast<float4*>(&sh[4 * NHR * TW + so]) = make_float4(axy[0], axy[1], axy[2], axy[3]);
        }
    }
    __syncthreads();

    // ---------------- Phase 2A: vertical conv of mu1, mu2 ----------------
    const int lr0 = ty * 4;
    const int scol = 4 * tx;

    float mu1[4][4], mu2[4][4];  // [vrow][col]
#pragma unroll
    for (int v = 0; v < 4; v++)
#pragma unroll
        for (int c = 0; c < 4; c++) { mu1[v][c] = 0.f; mu2[v][c] = 0.f; }

#pragma unroll
    for (int i = 0; i < 14; i++) {
        const float4 a = *reinterpret_cast<const float4*>(&sh[(0 * NHR + lr0 + i) * TW + scol]);
        const float4 b = *reinterpret_cast<const float4*>(&sh[(1 * NHR + lr0 + i) * TW + scol]);
        const float av[4] = {a.x, a.y, a.z, a.w};
        const float bv[4] = {b.x, b.y, b.z, b.w};
#pragma unroll
        for (int v = 0; v < 4; v++) {
            const int k = i - v;
            if (k >= 0 && k <= 10) {
                const float w = GW[k];
#pragma unroll
                for (int c = 0; c < 4; c++) {
                    mu1[v][c] = fmaf(w, av[c], mu1[v][c]);
                    mu2[v][c] = fmaf(w, bv[c], mu2[v][c]);
                }
            }
        }
    }

    // ---------------- Phase 2B: vertical conv of xx, yy, xy ----------------
    float sxx[4][4], syy[4][4], sxy[4][4];
#pragma unroll
    for (int v = 0; v < 4; v++)
#pragma unroll
        for (int c = 0; c < 4; c++) { sxx[v][c] = 0.f; syy[v][c] = 0.f; sxy[v][c] = 0.f; }

#pragma unroll
    for (int i = 0; i < 14; i++) {
        const float4 a = *reinterpret_cast<const float4*>(&sh[(2 * NHR + lr0 + i) * TW + scol]);
        const float4 b = *reinterpret_cast<const float4*>(&sh[(3 * NHR + lr0 + i) * TW + scol]);
        const float4 d = *reinterpret_cast<const float4*>(&sh[(4 * NHR + lr0 + i) * TW + scol]);
        const float av[4] = {a.x, a.y, a.z, a.w};
        const float bv[4] = {b.x, b.y, b.z, b.w};
        const float dv[4] = {d.x, d.y, d.z, d.w};
#pragma unroll
        for (int v = 0; v < 4; v++) {
            const int k = i - v;
            if (k >= 0 && k <= 10) {
                const float w = GW[k];
#pragma unroll
                for (int c = 0; c < 4; c++) {
                    sxx[v][c] = fmaf(w, av[c], sxx[v][c]);
                    syy[v][c] = fmaf(w, bv[c], syy[v][c]);
                    sxy[v][c] = fmaf(w, dv[c], sxy[v][c]);
                }
            }
        }
    }

    // ---------------- Epilogue + reduction ----------------
    float lsum = 0.0f;
    const float C1 = 1e-4f;      // (0.01)^2
    const float C2x4 = 0.0036f;  // 4*(0.03)^2 (sigmas unscaled by the 1/4 factor)
#pragma unroll
    for (int v = 0; v < 4; v++) {
        const int orow = r0 + lr0 + v;
#pragma unroll
        for (int c = 0; c < 4; c++) {
            const int ocol = basec + c;
            const float m1 = mu1[v][c];
            const float m2 = mu2[v][c];
            const float s1  = fmaf(-m1, m1, sxx[v][c]);
            const float s2  = fmaf(-m2, m2, syy[v][c]);
            const float s12 = fmaf(-m1, m2, sxy[v][c]);
            const float m1p = fmaf(0.5f, m1, 0.5f);
            const float m2p = fmaf(0.5f, m2, 0.5f);
            const float csn = fmaf(2.0f, s12, C2x4);
            const float csd = s1 + s2 + C2x4;
            const float t = m1p * m2p;
            const float ln = fmaf(2.0f, t, C1);
            const float ld = fmaf(m1p, m1p, fmaf(m2p, m2p, C1));
            const float ssim = (csn * ln) * __fdividef(1.0f, csd * ld);
            lsum += (orow < 502 && ocol < 502) ? ssim : 0.0f;
        }
    }

#pragma unroll
    for (int off = 16; off > 0; off >>= 1)
        lsum += __shfl_xor_sync(0xffffffffu, lsum, off);

    __shared__ float wsum[BY];
    if (tx == 0) wsum[ty] = lsum;
    __syncthreads();
    if (tx == 0 && ty == 0) {
        float b = 0.0f;
#pragma unroll
        for (int w = 0; w < BY; w++) b += wsum[w];
        const int bi = blockIdx.x + gridDim.x * (blockIdx.y + gridDim.y * blockIdx.z);
        g_partials[bi] = b;
    }
}

__global__ void ssim_reduce_kernel(float* __restrict__ out, double inv_count, int nblocks) {
    __shared__ double sd[32];
    double s = 0.0;
    for (int i = threadIdx.x; i < nblocks; i += blockDim.x)
        s += (double)g_partials[i];
#pragma unroll
    for (int off = 16; off > 0; off >>= 1)
        s += __shfl_xor_sync(0xffffffffu, s, off);
    if ((threadIdx.x & 31) == 0) sd[threadIdx.x >> 5] = s;
    __syncthreads();
    if (threadIdx.x < 32) {
        double v = (threadIdx.x < (blockDim.x >> 5)) ? sd[threadIdx.x] : 0.0;
#pragma unroll
        for (int off = 16; off > 0; off >>= 1)
            v += __shfl_xor_sync(0xffffffffu, v, off);
        if (threadIdx.x == 0) out[0] = (float)(v * inv_count);
    }
}

extern "C" void kernel_launch(void* const* d_in, const int* in_sizes, int n_in,
                              void* d_out, int out_size) {
    const float* X = (const float*)d_in[0];
    const float* Y = (const float*)d_in[1];
    float* out = (float*)d_out;

    const int images = in_sizes[0] / (512 * 512);  // N*C = 96
    const double count = (double)images * 502.0 * 502.0;

    const size_t smem = 5 * NHR * TW * sizeof(float);  // 107520 B
    cudaFuncSetAttribute(ssim_main_kernel,
                         cudaFuncAttributeMaxDynamicSharedMemorySize, (int)smem);

    dim3 grid(4, (502 + TH - 1) / TH, images);  // 4 x 16 x 96 = 6144 blocks
    dim3 block(BX, BY);
    ssim_main_kernel<<<grid, block, smem>>>(X, Y);

    const int nblocks = grid.x * grid.y * grid.z;
    ssim_reduce_kernel<<<1, 1024>>>(out, 1.0 / count, nblocks);
}